// round 16
// baseline (speedup 1.0000x reference)
#include <cuda_runtime.h>
#include <cuda_fp16.h>

#define NROWS   16384
#define INC     512
#define NG      64
#define NF      24
#define NO      16
#define ACCC    3584
#define RT      16
#define NTHR    512
#define TILE_BYTES (ACCC * RT * 2)        // 114688 (fp16 tile)
#define WPAD    388                        // padded words per group (384+4)
#define WSM_BYTES (NG * WPAD * 4)          // 99328
#define SMEM_ASK  (TILE_BYTES + WSM_BYTES) // 214016 -> 1 block/SM

typedef unsigned long long u64;

static __device__ __forceinline__ u64 pk2(float a, float b) {
    u64 r;
    asm("mov.b64 %0, {%1, %2};" : "=l"(r) : "f"(a), "f"(b));
    return r;
}
static __device__ __forceinline__ void up2(u64 v, float &a, float &b) {
    asm("mov.b64 {%0, %1}, %2;" : "=f"(a), "=f"(b) : "l"(v));
}
static __device__ __forceinline__ u64 fma2(u64 a, u64 b, u64 c) {
    u64 d;
    asm("fma.rn.f32x2 %0, %1, %2, %3;" : "=l"(d) : "l"(a), "l"(b), "l"(c));
    return d;
}
static __device__ __forceinline__ float tanhhw(float x) {
    float y;
    asm("tanh.approx.f32 %0, %1;" : "=f"(y) : "f"(x));
    return y;
}
static __device__ __forceinline__ float2 h2f(unsigned u) {
    __half2 h = reinterpret_cast<__half2&>(u);
    return __half22float2(h);
}

// fp16 tile [col][16 rows]: column = 32 B = 4 slots of 8 B (4 rows each).
// Slot s of column c lives at physical slot s ^ H2(c); H2 mixes col bits
// 2..5 so random gathers, staging stores and the writeback all bank-spread.
#define H2(c)  ((((c) >> 2) ^ ((c) >> 4)) & 3)

static __device__ __forceinline__ uint2* qp(uint2* tile, int c, int s) {
    return tile + c * 4 + (s ^ H2(c));
}

// Cooperative copy of one layer's weights W[64][24][16] fp32 into SMEM with
// group stride padded to WPAD words (bank-spreads the groups of a warp).
static __device__ __forceinline__ void stageW(const float* __restrict__ W,
                                              float* wsm, int t)
{
    const float4* src = reinterpret_cast<const float4*>(W);
    float4* dst = reinterpret_cast<float4*>(wsm);
    #pragma unroll
    for (int it = 0; it < 12; it++) {
        int i   = t + it * NTHR;       // 0..6143, fully coalesced LDG.128
        int row = i >> 2;              // (g,f) row 0..1535
        int k   = i & 3;
        int g   = row / NF;
        int f   = row - g * NF;
        dst[g * (WPAD / 4) + f * 4 + k] = __ldg(&src[i]);
    }
}

// Thread = (g, h, s): group g, o-half h (outputs 8h..8h+7), row-quad s
// (rows 4s..4s+3). Weights from SMEM (broadcast), depth-1 rolling prefetch.
// acc[r][j] = f32x2 over outputs (8h+2j, 8h+2j+1), local row r.
static __device__ __forceinline__ void glayer(uint2* tile,
                                              const float* wsm,
                                              int g, int h, int s,
                                              const float* __restrict__ bia,
                                              const int* __restrict__ idx,
                                              int colbase)
{
    int cols[NF];
    const int4* ip = reinterpret_cast<const int4*>(idx + g * NF);
    #pragma unroll
    for (int i = 0; i < NF / 4; i++) {
        int4 v = __ldg(&ip[i]);
        cols[4 * i + 0] = v.x; cols[4 * i + 1] = v.y;
        cols[4 * i + 2] = v.z; cols[4 * i + 3] = v.w;
    }

    u64 acc[4][4];
    {
        const float2* b2 = reinterpret_cast<const float2*>(bia + g * NO);
        #pragma unroll
        for (int j = 0; j < 4; j++) {
            float2 bb = __ldg(&b2[4 * h + j]);
            u64 bv = pk2(bb.x, bb.y);
            acc[0][j] = bv; acc[1][j] = bv; acc[2][j] = bv; acc[3][j] = bv;
        }
    }

    const ulonglong2* wg = reinterpret_cast<const ulonglong2*>(wsm + g * WPAD);

    // depth-1 prefetch (f = 0 primed): this thread's 32B o-half weight slice
    ulonglong2 cw0 = wg[2 * h];
    ulonglong2 cw1 = wg[2 * h + 1];
    uint2 ca = *qp(tile, cols[0], s);

    #pragma unroll
    for (int f = 0; f < NF; f++) {
        ulonglong2 nw0, nw1;
        uint2 na;
        if (f < NF - 1) {
            nw0 = wg[(f + 1) * 4 + 2 * h];
            nw1 = wg[(f + 1) * 4 + 2 * h + 1];
            na  = *qp(tile, cols[f + 1], s);
        }
        float2 r01 = h2f(ca.x), r23 = h2f(ca.y);
        u64 d0 = pk2(r01.x, r01.x), d1 = pk2(r01.y, r01.y);
        u64 d2 = pk2(r23.x, r23.x), d3 = pk2(r23.y, r23.y);
        u64 u0 = cw0.x, u1 = cw0.y, u2 = cw1.x, u3 = cw1.y;
        acc[0][0] = fma2(d0, u0, acc[0][0]); acc[0][1] = fma2(d0, u1, acc[0][1]);
        acc[0][2] = fma2(d0, u2, acc[0][2]); acc[0][3] = fma2(d0, u3, acc[0][3]);
        acc[1][0] = fma2(d1, u0, acc[1][0]); acc[1][1] = fma2(d1, u1, acc[1][1]);
        acc[1][2] = fma2(d1, u2, acc[1][2]); acc[1][3] = fma2(d1, u3, acc[1][3]);
        acc[2][0] = fma2(d2, u0, acc[2][0]); acc[2][1] = fma2(d2, u1, acc[2][1]);
        acc[2][2] = fma2(d2, u2, acc[2][2]); acc[2][3] = fma2(d2, u3, acc[2][3]);
        acc[3][0] = fma2(d3, u0, acc[3][0]); acc[3][1] = fma2(d3, u1, acc[3][1]);
        acc[3][2] = fma2(d3, u2, acc[3][2]); acc[3][3] = fma2(d3, u3, acc[3][3]);
        if (f < NF - 1) { cw0 = nw0; cw1 = nw1; ca = na; }
    }

    // tanh + fp16 writeback: 8 cols (this o-half) x 4 rows
    float v[4][8];
    #pragma unroll
    for (int r = 0; r < 4; r++)
        #pragma unroll
        for (int j = 0; j < 4; j++)
            up2(acc[r][j], v[r][2 * j], v[r][2 * j + 1]);
    #pragma unroll
    for (int r = 0; r < 4; r++)
        #pragma unroll
        for (int o = 0; o < 8; o++)
            v[r][o] = tanhhw(v[r][o]);
    #pragma unroll
    for (int o = 0; o < 8; o++) {
        int c = colbase + g * NO + 8 * h + o;
        __half2 p0 = __floats2half2_rn(v[0][o], v[1][o]);
        __half2 p1 = __floats2half2_rn(v[2][o], v[3][o]);
        uint2 st;
        st.x = reinterpret_cast<unsigned&>(p0);
        st.y = reinterpret_cast<unsigned&>(p1);
        *qp(tile, c, s) = st;
    }
}

__global__ void __launch_bounds__(NTHR, 1)
model_kernel(const float* __restrict__ x,
             const float* __restrict__ W1, const float* __restrict__ b1,
             const float* __restrict__ W2, const float* __restrict__ b2,
             const float* __restrict__ W3, const float* __restrict__ b3,
             const float* __restrict__ Wo, const float* __restrict__ bo,
             const int* __restrict__ idx1, const int* __restrict__ idx2,
             const int* __restrict__ idx3, const int* __restrict__ idxo,
             float* __restrict__ out)
{
    extern __shared__ char smemraw[];
    uint2* tile = reinterpret_cast<uint2*>(smemraw);              // fp16 tile
    float* wsm  = reinterpret_cast<float*>(smemraw + TILE_BYTES); // weights
    const int t = threadIdx.x;
    const int rowbase = blockIdx.x * RT;

    // ---- Stage x tile (16 rows x 512 cols) fp32->fp16 + W1 into SMEM ----
    {
        const float* xb = x + (size_t)rowbase * INC;
        #pragma unroll
        for (int k = 0; k < 4; k++) {
            int i  = t + k * NTHR;       // 0..2047
            int c  = i & 511;
            int qd = i >> 9;             // slot 0..3
            float r0 = __ldg(&xb[(4 * qd + 0) * INC + c]);
            float r1 = __ldg(&xb[(4 * qd + 1) * INC + c]);
            float r2 = __ldg(&xb[(4 * qd + 2) * INC + c]);
            float r3 = __ldg(&xb[(4 * qd + 3) * INC + c]);
            __half2 p0 = __floats2half2_rn(r0, r1);
            __half2 p1 = __floats2half2_rn(r2, r3);
            uint2 st;
            st.x = reinterpret_cast<unsigned&>(p0);
            st.y = reinterpret_cast<unsigned&>(p1);
            *qp(tile, c, qd) = st;
        }
        stageW(W1, wsm, t);
    }
    __syncthreads();

    const int g = t >> 3;         // group 0..63
    const int h = (t >> 2) & 1;   // o-half 0..1
    const int s = t & 3;          // row-quad 0..3

    glayer(tile, wsm, g, h, s, b1, idx1, 512);
    __syncthreads();
    stageW(W2, wsm, t);
    __syncthreads();
    glayer(tile, wsm, g, h, s, b2, idx2, 1536);
    __syncthreads();
    stageW(W3, wsm, t);
    __syncthreads();
    glayer(tile, wsm, g, h, s, b3, idx3, 2560);
    __syncthreads();

    // ---- Output layer: 4 groups x 48 f x 16 o, linear, fp32 out ----
    // thread = (ot, og, so): output col ot of group og, rows 2so..2so+1.
    {
        int ot = t & 15;
        int og = (t >> 4) & 3;
        int so = t >> 6;                 // row pair 0..7
        float bias = __ldg(&bo[og * 16 + ot]);
        u64 hacc = pk2(bias, bias);
        const int* gi = idxo + og * 48;
        const float* w = Wo + og * 48 * 16 + ot;
        #pragma unroll
        for (int f = 0; f < 48; f++) {
            int c = __ldg(&gi[f]);
            uint2 a = *qp(tile, c, so >> 1);
            unsigned halfw = (so & 1) ? a.y : a.x;
            float2 r = h2f(halfw);
            float wf = __ldg(&w[f * 16]);
            hacc = fma2(pk2(r.x, r.y), pk2(wf, wf), hacc);
        }
        float hv0, hv1;
        up2(hacc, hv0, hv1);
        float* ob = out + (size_t)(rowbase + 2 * so) * 64 + og * 16 + ot;
        ob[0]  = hv0;
        ob[64] = hv1;
    }
}

extern "C" void kernel_launch(void* const* d_in, const int* in_sizes, int n_in,
                              void* d_out, int out_size)
{
    const float* x   = (const float*)d_in[0];
    const float* W1  = (const float*)d_in[1];
    const float* b1  = (const float*)d_in[2];
    const float* W2  = (const float*)d_in[3];
    const float* b2  = (const float*)d_in[4];
    const float* W3  = (const float*)d_in[5];
    const float* b3  = (const float*)d_in[6];
    const float* Wo  = (const float*)d_in[7];
    const float* bo  = (const float*)d_in[8];
    const int*   i1  = (const int*)d_in[9];
    const int*   i2  = (const int*)d_in[10];
    const int*   i3  = (const int*)d_in[11];
    const int*   io  = (const int*)d_in[12];
    float*       out = (float*)d_out;

    cudaFuncSetAttribute(model_kernel,
                         cudaFuncAttributeMaxDynamicSharedMemorySize, SMEM_ASK);
    model_kernel<<<NROWS / RT, NTHR, SMEM_ASK>>>(
        x, W1, b1, W2, b2, W3, b3, Wo, bo, i1, i2, i3, io, out);
}

// round 17
// speedup vs baseline: 1.0799x; 1.0799x over previous
#include <cuda_runtime.h>
#include <cuda_fp16.h>

#define NROWS   16384
#define INC     512
#define NG      64
#define NF      24
#define NO      16
#define ACCC    3584
#define RT      16
#define NTHR    256
#define TILE_BYTES (ACCC * RT * 2)            // 114688 (fp16 tile)
#define WSTR    408                            // halves per group (384 + 24 pad)
#define WBUF_BYTES (NG * WSTR * 2)             // 52224
#define SMEM_ASK (TILE_BYTES + 2 * WBUF_BYTES) // 219136

typedef unsigned long long u64;

__device__ __half wscratch[3][NG * WSTR];      // fp16 weights, padded layout

static __device__ __forceinline__ u64 pk2(float a, float b) {
    u64 r;
    asm("mov.b64 %0, {%1, %2};" : "=l"(r) : "f"(a), "f"(b));
    return r;
}
static __device__ __forceinline__ void up2(u64 v, float &a, float &b) {
    asm("mov.b64 {%0, %1}, %2;" : "=f"(a), "=f"(b) : "l"(v));
}
static __device__ __forceinline__ u64 fma2(u64 a, u64 b, u64 c) {
    u64 d;
    asm("fma.rn.f32x2 %0, %1, %2, %3;" : "=l"(d) : "l"(a), "l"(b), "l"(c));
    return d;
}
static __device__ __forceinline__ float tanhhw(float x) {
    float y;
    asm("tanh.approx.f32 %0, %1;" : "=f"(y) : "f"(x));
    return y;
}
static __device__ __forceinline__ float2 h2f(unsigned u) {
    __half2 h = reinterpret_cast<__half2&>(u);
    return __half22float2(h);
}
static __device__ __forceinline__ void cpasync16(unsigned dst, const void* src) {
    asm volatile("cp.async.ca.shared.global [%0], [%1], 16;" :: "r"(dst), "l"(src));
}
#define CP_COMMIT() asm volatile("cp.async.commit_group;" ::: "memory")
#define CP_WAIT(n)  asm volatile("cp.async.wait_group %0;" :: "n"(n) : "memory")

// fp16 tile [col][16 rows]: column = 32 B = 4 slots of 8 B (4 rows each).
// Slot s of column c lives at physical slot s ^ H2(c).
#define H2(c)  ((((c) >> 2) ^ ((c) >> 4)) & 3)
#define AOFF(c, s) ((unsigned)((c) * 32 + (((s) ^ H2(c)) << 3)))

// ---- prepass: convert W1..W3 fp32 -> fp16 scratch (padded stride) ----
__global__ void convW_kernel(const float* __restrict__ W1,
                             const float* __restrict__ W2,
                             const float* __restrict__ W3)
{
    int i = blockIdx.x * blockDim.x + threadIdx.x;     // over 3*64*384
    if (i >= 3 * NG * NF * NO) return;
    int L  = i / (NG * NF * NO);
    int r  = i % (NG * NF * NO);
    int g  = r / (NF * NO);
    int fo = r % (NF * NO);
    const float* W = (L == 0) ? W1 : ((L == 1) ? W2 : W3);
    wscratch[L][g * WSTR + fo] = __float2half_rn(W[(size_t)g * NF * NO + fo]);
}

// Thread = (g, s): group g, row-quad s (rows 4s..4s+3), all 16 outputs.
// Weights from fp16 SMEM buffer (broadcast LDS.128), depth-1 prefetch.
static __device__ __forceinline__ void glayer(char* tilec,
                                              const __half* wbuf,
                                              int g, int s,
                                              const float* __restrict__ bia,
                                              const int* __restrict__ idx,
                                              int colbase)
{
    unsigned aoff[NF];                       // gather byte offsets (hash folded)
    const int4* ip = reinterpret_cast<const int4*>(idx + g * NF);
    #pragma unroll
    for (int i = 0; i < NF / 4; i++) {
        int4 v = __ldg(&ip[i]);
        int cs[4] = {v.x, v.y, v.z, v.w};
        #pragma unroll
        for (int k = 0; k < 4; k++)
            aoff[4 * i + k] = AOFF(cs[k], s);
    }

    u64 acc[4][8];
    {
        const float2* b2 = reinterpret_cast<const float2*>(bia + g * NO);
        #pragma unroll
        for (int op = 0; op < 8; op++) {
            float2 bb = __ldg(&b2[op]);
            u64 bv = pk2(bb.x, bb.y);
            acc[0][op] = bv; acc[1][op] = bv; acc[2][op] = bv; acc[3][op] = bv;
        }
    }

    const char* wg = reinterpret_cast<const char*>(wbuf + g * WSTR);

    // depth-1 prefetch (f = 0 primed): 32B of fp16 weights + 8B activations
    uint4 w0 = *reinterpret_cast<const uint4*>(wg);
    uint4 w1 = *reinterpret_cast<const uint4*>(wg + 16);
    uint2 ca = *reinterpret_cast<const uint2*>(tilec + aoff[0]);

    #pragma unroll
    for (int f = 0; f < NF; f++) {
        uint4 nw0, nw1;
        uint2 na;
        if (f < NF - 1) {
            nw0 = *reinterpret_cast<const uint4*>(wg + (f + 1) * 32);
            nw1 = *reinterpret_cast<const uint4*>(wg + (f + 1) * 32 + 16);
            na  = *reinterpret_cast<const uint2*>(tilec + aoff[f + 1]);
        }
        float2 r01 = h2f(ca.x), r23 = h2f(ca.y);
        u64 d0 = pk2(r01.x, r01.x), d1 = pk2(r01.y, r01.y);
        u64 d2 = pk2(r23.x, r23.x), d3 = pk2(r23.y, r23.y);
        u64 wp[8];
        {
            float2 q;
            q = h2f(w0.x); wp[0] = pk2(q.x, q.y);
            q = h2f(w0.y); wp[1] = pk2(q.x, q.y);
            q = h2f(w0.z); wp[2] = pk2(q.x, q.y);
            q = h2f(w0.w); wp[3] = pk2(q.x, q.y);
            q = h2f(w1.x); wp[4] = pk2(q.x, q.y);
            q = h2f(w1.y); wp[5] = pk2(q.x, q.y);
            q = h2f(w1.z); wp[6] = pk2(q.x, q.y);
            q = h2f(w1.w); wp[7] = pk2(q.x, q.y);
        }
        #pragma unroll
        for (int op = 0; op < 8; op++) {
            acc[0][op] = fma2(d0, wp[op], acc[0][op]);
            acc[1][op] = fma2(d1, wp[op], acc[1][op]);
            acc[2][op] = fma2(d2, wp[op], acc[2][op]);
            acc[3][op] = fma2(d3, wp[op], acc[3][op]);
        }
        if (f < NF - 1) { w0 = nw0; w1 = nw1; ca = na; }
    }

    // tanh + fp16 writeback: 16 cols x 4 rows
    float v[4][NO];
    #pragma unroll
    for (int r = 0; r < 4; r++)
        #pragma unroll
        for (int op = 0; op < 8; op++)
            up2(acc[r][op], v[r][2 * op], v[r][2 * op + 1]);
    #pragma unroll
    for (int r = 0; r < 4; r++)
        #pragma unroll
        for (int o = 0; o < NO; o++)
            v[r][o] = tanhhw(v[r][o]);
    #pragma unroll
    for (int o = 0; o < NO; o++) {
        int c = colbase + g * NO + o;
        __half2 p0 = __floats2half2_rn(v[0][o], v[1][o]);
        __half2 p1 = __floats2half2_rn(v[2][o], v[3][o]);
        uint2 st;
        st.x = reinterpret_cast<unsigned&>(p0);
        st.y = reinterpret_cast<unsigned&>(p1);
        *reinterpret_cast<uint2*>(tilec + AOFF(c, s)) = st;
    }
}

static __device__ __forceinline__ void kickW(unsigned dst, const __half* src,
                                             int t)
{
    const char* sp = reinterpret_cast<const char*>(src);
    for (int i = t; i < WBUF_BYTES / 16; i += NTHR)
        cpasync16(dst + i * 16, sp + i * 16);
    CP_COMMIT();
}

__global__ void __launch_bounds__(NTHR, 1)
model_kernel(const float* __restrict__ x,
             const float* __restrict__ b1, const float* __restrict__ b2,
             const float* __restrict__ b3,
             const float* __restrict__ Wo, const float* __restrict__ bo,
             const int* __restrict__ idx1, const int* __restrict__ idx2,
             const int* __restrict__ idx3, const int* __restrict__ idxo,
             float* __restrict__ out)
{
    extern __shared__ char smemraw[];
    char*   tilec = smemraw;
    __half* wb0   = reinterpret_cast<__half*>(smemraw + TILE_BYTES);
    __half* wb1   = reinterpret_cast<__half*>(smemraw + TILE_BYTES + WBUF_BYTES);
    const unsigned d0 = (unsigned)__cvta_generic_to_shared(wb0);
    const unsigned d1 = (unsigned)__cvta_generic_to_shared(wb1);
    const int t = threadIdx.x;
    const int rowbase = blockIdx.x * RT;

    // ---- kick async weight copies for layers 1 & 2 (background DMA) ----
    kickW(d0, wscratch[0], t);   // group 0: W1 -> buf0
    kickW(d1, wscratch[1], t);   // group 1: W2 -> buf1

    // ---- Stage x tile (16 rows x 512 cols) fp32->fp16 into SMEM ----
    {
        const float* xb = x + (size_t)rowbase * INC;
        #pragma unroll
        for (int k = 0; k < 8; k++) {
            int i  = t + k * NTHR;       // 0..2047
            int c  = i & 511;
            int qd = i >> 9;             // slot 0..3
            float r0 = __ldcs(&xb[(4 * qd + 0) * INC + c]);
            float r1 = __ldcs(&xb[(4 * qd + 1) * INC + c]);
            float r2 = __ldcs(&xb[(4 * qd + 2) * INC + c]);
            float r3 = __ldcs(&xb[(4 * qd + 3) * INC + c]);
            __half2 p0 = __floats2half2_rn(r0, r1);
            __half2 p1 = __floats2half2_rn(r2, r3);
            uint2 st;
            st.x = reinterpret_cast<unsigned&>(p0);
            st.y = reinterpret_cast<unsigned&>(p1);
            *reinterpret_cast<uint2*>(tilec + AOFF(c, qd)) = st;
        }
    }
    CP_WAIT(1);            // W1 landed (W2 may still be in flight)
    __syncthreads();

    const int g = t >> 2;   // group 0..63
    const int s = t & 3;    // row-quad 0..3

    glayer(tilec, wb0, g, s, b1, idx1, 512);
    __syncthreads();                     // buf0 readers done, tile visible
    kickW(d0, wscratch[2], t);           // group 2: W3 -> buf0 (hidden under L2)
    CP_WAIT(1);                          // W2 landed (W3 may pend)
    __syncthreads();
    glayer(tilec, wb1, g, s, b2, idx2, 1536);
    CP_WAIT(0);                          // W3 landed
    __syncthreads();
    glayer(tilec, wb0, g, s, b3, idx3, 2560);
    __syncthreads();

    // ---- Output layer: 4 groups x 48 f x 16 o, linear, fp32 out ----
    {
        int ot = t & 15;
        int og = (t >> 4) & 3;
        int so = t >> 6;                 // row-quad 0..3
        float bias = __ldg(&bo[og * 16 + ot]);
        u64 bd = pk2(bias, bias);
        u64 h01 = bd, h23 = bd;
        const int* gi = idxo + og * 48;
        const float* w = Wo + og * 48 * 16 + ot;
        #pragma unroll
        for (int f = 0; f < 48; f++) {
            int c = __ldg(&gi[f]);
            uint2 a = *reinterpret_cast<const uint2*>(tilec + AOFF(c, so));
            float2 r01 = h2f(a.x), r23 = h2f(a.y);
            float wf = __ldg(&w[f * 16]);
            u64 wd = pk2(wf, wf);
            h01 = fma2(pk2(r01.x, r01.y), wd, h01);
            h23 = fma2(pk2(r23.x, r23.y), wd, h23);
        }
        float hv[4];
        up2(h01, hv[0], hv[1]);
        up2(h23, hv[2], hv[3]);
        float* ob = out + (size_t)(rowbase + 4 * so) * 64 + og * 16 + ot;
        ob[0]   = hv[0];
        ob[64]  = hv[1];
        ob[128] = hv[2];
        ob[192] = hv[3];
    }
}

extern "C" void kernel_launch(void* const* d_in, const int* in_sizes, int n_in,
                              void* d_out, int out_size)
{
    const float* x   = (const float*)d_in[0];
    const float* W1  = (const float*)d_in[1];
    const float* b1  = (const float*)d_in[2];
    const float* W2  = (const float*)d_in[3];
    const float* b2  = (const float*)d_in[4];
    const float* W3  = (const float*)d_in[5];
    const float* b3  = (const float*)d_in[6];
    const float* Wo  = (const float*)d_in[7];
    const float* bo  = (const float*)d_in[8];
    const int*   i1  = (const int*)d_in[9];
    const int*   i2  = (const int*)d_in[10];
    const int*   i3  = (const int*)d_in[11];
    const int*   io  = (const int*)d_in[12];
    float*       out = (float*)d_out;

    // prepass: fp32 -> fp16 padded weight scratch (3*64*384 elements)
    convW_kernel<<<(3 * NG * NF * NO + 255) / 256, 256>>>(W1, W2, W3);

    cudaFuncSetAttribute(model_kernel,
                         cudaFuncAttributeMaxDynamicSharedMemorySize, SMEM_ASK);
    model_kernel<<<NROWS / RT, NTHR, SMEM_ASK>>>(
        x, b1, b2, b3, Wo, bo, i1, i2, i3, io, out);
}